// round 7
// baseline (speedup 1.0000x reference)
#include <cuda_runtime.h>
#include <math.h>

// ---------------------------------------------------------------------------
// BNAF forward: D=8, H=512, B=2048, 4 masked layers + tanh, with log-det flow.
//
// Identities used:
//  * diag-block exp(ld) == normalized weight w  =>  logsumexp(sld + ld) =
//      m + log( exp(sld-m) . w_diag )   (plain dot product, no per-pair exp)
//  * with E = exp(-2|y|), r = 1/(1+E):
//      tanh(y) = sign(y)*(1-E)*r ;  sld_out = m + 2ln2 - 2|y| + log(Q*r^2)
// ---------------------------------------------------------------------------

#define B_  2048
#define H_  512
#define D_  8
#define TWO_LN2 1.38629436111989062f

// scratch (device globals; no allocation allowed)
__device__ float g_wT1[8 * 512];      // [in][out]
__device__ float g_wT2[512 * 512];    // [in][out]
__device__ float g_wT3[512 * 512];    // [in][out]
__device__ float g_w4n[8 * 512];      // [out][in] (natural)
__device__ float g_logw1d[512];
__device__ float g_h1[B_ * H_];
__device__ float g_h2[B_ * H_];
__device__ float g_h3[B_ * H_];
__device__ float g_sldA[B_ * H_];     // [b][i*64+o]
__device__ float g_sldB[B_ * H_];

// ---------------------------------------------------------------------------
// merged prep: all 4 layers in ONE launch.
// ---------------------------------------------------------------------------
__global__ void prep_all_kernel(const float* __restrict__ W1, const float* __restrict__ g1,
                                const float* __restrict__ W2, const float* __restrict__ g2,
                                const float* __restrict__ W3, const float* __restrict__ g3,
                                const float* __restrict__ W4, const float* __restrict__ g4) {
    int blk = blockIdx.x;
    const float *W, *logg; int IN, OUT, ibshift, ob, layer, row0;
    if (blk < 64)       { layer = 1; W = W1; logg = g1; IN = 8;   OUT = 512; ibshift = 0; ob = 64; row0 = blk * 8; }
    else if (blk < 128) { layer = 2; W = W2; logg = g2; IN = 512; OUT = 512; ibshift = 6; ob = 64; row0 = (blk - 64) * 8; }
    else if (blk < 192) { layer = 3; W = W3; logg = g3; IN = 512; OUT = 512; ibshift = 6; ob = 64; row0 = (blk - 128) * 8; }
    else                { layer = 4; W = W4; logg = g4; IN = 512; OUT = 8;   ibshift = 6; ob = 1;  row0 = 0; }

    int o = row0 + threadIdx.y;
    if (o >= OUT) return;
    int lane = threadIdx.x;
    int i = o / ob;

    float sq = 0.0f;
    for (int c = lane; c < IN; c += 32) {
        int jb = c >> ibshift;
        float wv = W[o * IN + c];
        float v  = (jb == i) ? expf(wv) : (jb < i ? wv : 0.0f);
        sq += v * v;
    }
    #pragma unroll
    for (int off = 16; off; off >>= 1)
        sq += __shfl_xor_sync(0xffffffffu, sq, off);

    float scale = expf(logg[o]) / sqrtf(sq);
    for (int c = lane; c < IN; c += 32) {
        int jb = c >> ibshift;
        float wv = W[o * IN + c];
        float v  = (jb == i) ? expf(wv) : (jb < i ? wv : 0.0f);
        float w  = v * scale;
        if (layer == 1) {
            g_wT1[c * 512 + o] = w;
            if (c == i) g_logw1d[o] = logf(w);
        } else if (layer == 2) {
            g_wT2[c * 512 + o] = w;
        } else if (layer == 3) {
            g_wT3[c * 512 + o] = w;
        } else {
            g_w4n[o * 512 + c] = w;
        }
    }
}

// ---------------------------------------------------------------------------
// layer 1: per block 8 batch rows; weight column cached in registers.
// ---------------------------------------------------------------------------
__global__ void gemm1_kernel(const float* __restrict__ x,
                             const float* __restrict__ bias) {
    __shared__ float xs[8][8];
    int og = threadIdx.x;
    int b0 = blockIdx.x * 8;

    float w[8];
    #pragma unroll
    for (int k = 0; k < 8; k++) w[k] = g_wT1[k * 512 + og];
    float lw = g_logw1d[og];
    float bz = bias[og];

    if (og < 64) xs[og >> 3][og & 7] = x[b0 * 8 + og];
    __syncthreads();

    #pragma unroll
    for (int r = 0; r < 8; r++) {
        float acc = bz;
        #pragma unroll
        for (int k = 0; k < 8; k++) acc += w[k] * xs[r][k];
        float ay = fabsf(acc);
        float E  = __expf(-2.0f * ay);
        float rc = __fdividef(1.0f, 1.0f + E);
        int b = b0 + r;
        g_h1[b * 512 + og]   = copysignf((1.0f - E) * rc, acc);
        g_sldA[b * 512 + og] = lw + TWO_LN2 - 2.0f * ay + __logf(rc * rc);
    }
}

// ---------------------------------------------------------------------------
// fused middle layer (2,3): masked GEMM + tanh + sld logsumexp update.
// BM=BN=64, BK=32, 128 threads, 8x4/thread (FMA-bound: 48B LDS / 32 FMA / k).
// Item t (0..255): i = 7-(t>>5), m-block = t&31, work weight = i+1.
// Grid 304 (2 CTAs/SM): bid<152 -> t=bid (heavy-first); bid 152..255 ->
// t=407-bid (light tail, reversed). With modulo CTA placement each SM's pair
// of items sums to ~9 weight units -> balanced, 16 warps/SM hide latency.
// Smem union: As/Bs double buffers alias epilogue's Ps/wdS.
// ---------------------------------------------------------------------------
__global__ __launch_bounds__(128) void layer_mid_kernel(int layer,
                                                        const float* __restrict__ bias) {
    const float* A    = (layer == 2) ? g_h1  : g_h2;
    const float* wT   = (layer == 2) ? g_wT2 : g_wT3;
    float*       Hout = (layer == 2) ? g_h2  : g_h3;
    const float* Sin  = (layer == 2) ? g_sldA : g_sldB;
    float*       Sout = (layer == 2) ? g_sldB : g_sldA;

    __shared__ __align__(16) float blob[2 * 2 * 32 * 68];   // 34816 B
    __shared__ float mrow[64];

    float (*As)[32][68] = (float (*)[32][68])(blob);
    float (*Bs)[32][68] = (float (*)[32][68])(blob + 2 * 32 * 68);
    float (*Ps)[68]     = (float (*)[68])(blob);             // 64x68
    float (*wdS)[68]    = (float (*)[68])(blob + 2 * 32 * 68); // 64x68

    int bid = blockIdx.x;
    int t;
    if (bid < 152)      t = bid;            // heavy-first: weight 8-(t>>5)
    else if (bid < 256) t = 407 - bid;      // light tail reversed
    else return;

    int i  = 7 - (t >> 5);
    int n0 = i * 64;
    int m0 = (t & 31) * 64;
    int ntiles = (i + 1) * 2;               // BK=32 tiles (mask skip)

    int tid = threadIdx.x;
    int tx = tid & 15, ty = tid >> 4;       // 8x4 output tile map
    int am = tid >> 1, ak = (tid & 1) * 16; // A-load: row am, 16 k's
    int bk = tid >> 2, bn = (tid & 3) * 16; // B-load: k-row bk, 16 n's

    const float* Aptr = A  + (m0 + am) * 512 + ak;
    const float* Bptr = wT + bk * 512 + n0 + bn;

    float4 pa[4], pb[4];
    #pragma unroll
    for (int c = 0; c < 4; c++) {
        pa[c] = *(const float4*)(Aptr + c * 4);
        pb[c] = *(const float4*)(Bptr + c * 4);
    }
    #pragma unroll
    for (int c = 0; c < 4; c++) {
        As[0][ak + c * 4 + 0][am] = pa[c].x;
        As[0][ak + c * 4 + 1][am] = pa[c].y;
        As[0][ak + c * 4 + 2][am] = pa[c].z;
        As[0][ak + c * 4 + 3][am] = pa[c].w;
        *(float4*)(&Bs[0][bk][bn + c * 4]) = pb[c];
    }
    __syncthreads();

    float acc[8][4] = {};

    for (int kt = 0; kt < ntiles; kt++) {
        int cur = kt & 1;
        bool more = (kt + 1 < ntiles);
        if (more) {
            int k0 = (kt + 1) * 32;
            #pragma unroll
            for (int c = 0; c < 4; c++) {
                pa[c] = *(const float4*)(Aptr + k0 + c * 4);
                pb[c] = *(const float4*)(Bptr + k0 * 512 + c * 4);
            }
        }
        #pragma unroll 8
        for (int k = 0; k < 32; k++) {
            float4 a0 = *(const float4*)(&As[cur][k][ty * 8]);
            float4 a1 = *(const float4*)(&As[cur][k][ty * 8 + 4]);
            float4 b  = *(const float4*)(&Bs[cur][k][tx * 4]);
            acc[0][0] += a0.x * b.x; acc[0][1] += a0.x * b.y;
            acc[0][2] += a0.x * b.z; acc[0][3] += a0.x * b.w;
            acc[1][0] += a0.y * b.x; acc[1][1] += a0.y * b.y;
            acc[1][2] += a0.y * b.z; acc[1][3] += a0.y * b.w;
            acc[2][0] += a0.z * b.x; acc[2][1] += a0.z * b.y;
            acc[2][2] += a0.z * b.z; acc[2][3] += a0.z * b.w;
            acc[3][0] += a0.w * b.x; acc[3][1] += a0.w * b.y;
            acc[3][2] += a0.w * b.z; acc[3][3] += a0.w * b.w;
            acc[4][0] += a1.x * b.x; acc[4][1] += a1.x * b.y;
            acc[4][2] += a1.x * b.z; acc[4][3] += a1.x * b.w;
            acc[5][0] += a1.y * b.x; acc[5][1] += a1.y * b.y;
            acc[5][2] += a1.y * b.z; acc[5][3] += a1.y * b.w;
            acc[6][0] += a1.z * b.x; acc[6][1] += a1.z * b.y;
            acc[6][2] += a1.z * b.z; acc[6][3] += a1.z * b.w;
            acc[7][0] += a1.w * b.x; acc[7][1] += a1.w * b.y;
            acc[7][2] += a1.w * b.z; acc[7][3] += a1.w * b.w;
        }
        if (more) {
            int nxt = cur ^ 1;
            #pragma unroll
            for (int c = 0; c < 4; c++) {
                As[nxt][ak + c * 4 + 0][am] = pa[c].x;
                As[nxt][ak + c * 4 + 1][am] = pa[c].y;
                As[nxt][ak + c * 4 + 2][am] = pa[c].z;
                As[nxt][ak + c * 4 + 3][am] = pa[c].w;
                *(float4*)(&Bs[nxt][bk][bn + c * 4]) = pb[c];
            }
        }
        __syncthreads();
    }
    // blob free now -> epilogue reuses it as Ps/wdS.

    // sld tile: row = tid>>1, half q = tid&1 covers 32 cols.
    int row = tid >> 1, q = tid & 1;
    const float4* sp = (const float4*)(Sin + (m0 + row) * 512 + n0 + q * 32);
    float4 v4[8];
    float mx = -1e30f;
    #pragma unroll
    for (int c = 0; c < 8; c++) {
        v4[c] = sp[c];
        mx = fmaxf(mx, fmaxf(fmaxf(v4[c].x, v4[c].y), fmaxf(v4[c].z, v4[c].w)));
    }
    float mr_own = fmaxf(mx, __shfl_xor_sync(0xffffffffu, mx, 1)); // pair thread
    mrow[row] = mr_own;

    #pragma unroll
    for (int c = 0; c < 8; c++) {
        int j = q * 32 + c * 4;
        Ps[j + 0][row] = __expf(v4[c].x - mr_own);
        Ps[j + 1][row] = __expf(v4[c].y - mr_own);
        Ps[j + 2][row] = __expf(v4[c].z - mr_own);
        Ps[j + 3][row] = __expf(v4[c].w - mr_own);
    }
    // diag weight block from L2: wdS[j][o] = wT[(n0+j)*512 + n0+o]
    for (int idx = tid; idx < 4096; idx += 128) {
        int o = idx & 63, j = idx >> 6;
        wdS[j][o] = wT[(n0 + j) * 512 + n0 + o];
    }
    __syncthreads();

    // mini-GEMM: Q[m][o] = sum_j P[m][j] * wd[o][j]
    float qacc[8][4] = {};
    #pragma unroll 8
    for (int j = 0; j < 64; j++) {
        float4 a0 = *(const float4*)(&Ps[j][ty * 8]);
        float4 a1 = *(const float4*)(&Ps[j][ty * 8 + 4]);
        float4 b  = *(const float4*)(&wdS[j][tx * 4]);
        qacc[0][0] += a0.x * b.x; qacc[0][1] += a0.x * b.y;
        qacc[0][2] += a0.x * b.z; qacc[0][3] += a0.x * b.w;
        qacc[1][0] += a0.y * b.x; qacc[1][1] += a0.y * b.y;
        qacc[1][2] += a0.y * b.z; qacc[1][3] += a0.y * b.w;
        qacc[2][0] += a0.z * b.x; qacc[2][1] += a0.z * b.y;
        qacc[2][2] += a0.z * b.z; qacc[2][3] += a0.z * b.w;
        qacc[3][0] += a0.w * b.x; qacc[3][1] += a0.w * b.y;
        qacc[3][2] += a0.w * b.z; qacc[3][3] += a0.w * b.w;
        qacc[4][0] += a1.x * b.x; qacc[4][1] += a1.x * b.y;
        qacc[4][2] += a1.x * b.z; qacc[4][3] += a1.x * b.w;
        qacc[5][0] += a1.y * b.x; qacc[5][1] += a1.y * b.y;
        qacc[5][2] += a1.y * b.z; qacc[5][3] += a1.y * b.w;
        qacc[6][0] += a1.z * b.x; qacc[6][1] += a1.z * b.y;
        qacc[6][2] += a1.z * b.z; qacc[6][3] += a1.z * b.w;
        qacc[7][0] += a1.w * b.x; qacc[7][1] += a1.w * b.y;
        qacc[7][2] += a1.w * b.z; qacc[7][3] += a1.w * b.w;
    }

    // epilogue: h = tanh(y), sld_out in one logf; vectorized stores
    float4 bz = *(const float4*)(bias + n0 + tx * 4);
    float bzv[4] = {bz.x, bz.y, bz.z, bz.w};
    #pragma unroll
    for (int ii = 0; ii < 8; ii++) {
        int m = m0 + ty * 8 + ii;
        float mr = mrow[ty * 8 + ii];
        float4 h4, s4;
        float* hp = (float*)&h4;
        float* spv = (float*)&s4;
        #pragma unroll
        for (int jj = 0; jj < 4; jj++) {
            float y  = acc[ii][jj] + bzv[jj];
            float ay = fabsf(y);
            float E  = __expf(-2.0f * ay);
            float rc = __fdividef(1.0f, 1.0f + E);
            hp[jj]  = copysignf((1.0f - E) * rc, y);
            spv[jj] = mr + TWO_LN2 - 2.0f * ay + __logf(qacc[ii][jj] * rc * rc);
        }
        *(float4*)(&Hout[m * 512 + n0 + tx * 4]) = h4;
        *(float4*)(&Sout[m * 512 + n0 + tx * 4]) = s4;
    }
}

// ---------------------------------------------------------------------------
// fused layer 4: block handles 8 batch rows; w4 cached in smem once.
// warp i handles data dim i: 512-dot + tanh -> out[0:16384]; sld finale ->
// out[16384:32768].
// ---------------------------------------------------------------------------
__global__ void layer_last_kernel(const float* __restrict__ bias,
                                  float* __restrict__ out) {
    __shared__ float wsm[8 * 512];
    int tid = threadIdx.x;
    for (int idx = tid; idx < 4096; idx += 256) wsm[idx] = g_w4n[idx];
    __syncthreads();

    int i = tid >> 5, lane = tid & 31;
    float bz = bias[i];
    float wd0 = wsm[i * 512 + i * 64 + lane];
    float wd1 = wsm[i * 512 + i * 64 + lane + 32];

    int b0 = blockIdx.x * 8;
    #pragma unroll
    for (int r = 0; r < 8; r++) {
        int b = b0 + r;
        const float* hp = g_h3 + b * 512;
        float acc = 0.0f;
        #pragma unroll 4
        for (int k = lane; k < 512; k += 32) acc += hp[k] * wsm[i * 512 + k];
        #pragma unroll
        for (int off = 16; off; off >>= 1)
            acc += __shfl_xor_sync(0xffffffffu, acc, off);

        float y  = acc + bz;
        float ay = fabsf(y);
        float E  = __expf(-2.0f * ay);
        float rc = __fdividef(1.0f, 1.0f + E);

        const float* sp = g_sldA + b * 512 + i * 64;
        float s0 = sp[lane], s1 = sp[lane + 32];
        float m = fmaxf(s0, s1);
        #pragma unroll
        for (int off = 16; off; off >>= 1)
            m = fmaxf(m, __shfl_xor_sync(0xffffffffu, m, off));
        float p0 = __expf(s0 - m), p1 = __expf(s1 - m);
        float a = p0 * wd0 + p1 * wd1;
        #pragma unroll
        for (int off = 16; off; off >>= 1)
            a += __shfl_xor_sync(0xffffffffu, a, off);

        if (lane == 0) {
            out[b * 8 + i]           = copysignf((1.0f - E) * rc, y);
            out[B_ * D_ + b * 8 + i] = m + TWO_LN2 - 2.0f * ay + __logf(a * rc * rc);
        }
    }
}

// ---------------------------------------------------------------------------
extern "C" void kernel_launch(void* const* d_in, const int* in_sizes, int n_in,
                              void* d_out, int out_size) {
    (void)in_sizes; (void)n_in; (void)out_size;
    const float* x  = (const float*)d_in[0];
    const float* W1 = (const float*)d_in[1];
    const float* g1 = (const float*)d_in[2];
    const float* b1 = (const float*)d_in[3];
    const float* W2 = (const float*)d_in[4];
    const float* g2 = (const float*)d_in[5];
    const float* b2 = (const float*)d_in[6];
    const float* W3 = (const float*)d_in[7];
    const float* g3 = (const float*)d_in[8];
    const float* b3 = (const float*)d_in[9];
    const float* W4 = (const float*)d_in[10];
    const float* g4 = (const float*)d_in[11];
    const float* b4 = (const float*)d_in[12];
    float* out = (float*)d_out;

    prep_all_kernel<<<193, dim3(32, 8)>>>(W1, g1, W2, g2, W3, g3, W4, g4);
    gemm1_kernel<<<256, 512>>>(x, b1);
    layer_mid_kernel<<<304, 128>>>(2, b2);
    layer_mid_kernel<<<304, 128>>>(3, b3);
    layer_last_kernel<<<256, 256>>>(b4, out);
}

// round 8
// speedup vs baseline: 1.2161x; 1.2161x over previous
#include <cuda_runtime.h>
#include <math.h>

// ---------------------------------------------------------------------------
// BNAF forward: D=8, H=512, B=2048, 4 masked layers + tanh, with log-det flow.
//
// Identities used:
//  * diag-block exp(ld) == normalized weight w  =>  logsumexp(sld + ld) =
//      m + log( exp(sld-m) . w_diag )   (plain dot product, no per-pair exp)
//  * with E = exp(-2|y|), r = 1/(1+E):
//      tanh(y) = sign(y)*(1-E)*r ;  sld_out = m + 2ln2 - 2|y| + log(Q*r^2)
// ---------------------------------------------------------------------------

#define B_  2048
#define H_  512
#define D_  8
#define TWO_LN2 1.38629436111989062f
#define NSM 152          // persistent grid size for layer_mid

// scratch (device globals; no allocation allowed)
__device__ float g_wT1[8 * 512];      // [in][out]
__device__ float g_wT2[512 * 512];    // [in][out]
__device__ float g_wT3[512 * 512];    // [in][out]
__device__ float g_w4n[8 * 512];      // [out][in] (natural)
__device__ float g_logw1d[512];
__device__ float g_h1[B_ * H_];
__device__ float g_h2[B_ * H_];
__device__ float g_h3[B_ * H_];
__device__ float g_sldA[B_ * H_];     // [b][i*64+o]
__device__ float g_sldB[B_ * H_];

// ---------------------------------------------------------------------------
// merged prep: all 4 layers in ONE launch.
// ---------------------------------------------------------------------------
__global__ void prep_all_kernel(const float* __restrict__ W1, const float* __restrict__ g1,
                                const float* __restrict__ W2, const float* __restrict__ g2,
                                const float* __restrict__ W3, const float* __restrict__ g3,
                                const float* __restrict__ W4, const float* __restrict__ g4) {
    int blk = blockIdx.x;
    const float *W, *logg; int IN, OUT, ibshift, ob, layer, row0;
    if (blk < 64)       { layer = 1; W = W1; logg = g1; IN = 8;   OUT = 512; ibshift = 0; ob = 64; row0 = blk * 8; }
    else if (blk < 128) { layer = 2; W = W2; logg = g2; IN = 512; OUT = 512; ibshift = 6; ob = 64; row0 = (blk - 64) * 8; }
    else if (blk < 192) { layer = 3; W = W3; logg = g3; IN = 512; OUT = 512; ibshift = 6; ob = 64; row0 = (blk - 128) * 8; }
    else                { layer = 4; W = W4; logg = g4; IN = 512; OUT = 8;   ibshift = 6; ob = 1;  row0 = 0; }

    int o = row0 + threadIdx.y;
    if (o >= OUT) return;
    int lane = threadIdx.x;
    int i = o / ob;

    float sq = 0.0f;
    for (int c = lane; c < IN; c += 32) {
        int jb = c >> ibshift;
        float wv = W[o * IN + c];
        float v  = (jb == i) ? expf(wv) : (jb < i ? wv : 0.0f);
        sq += v * v;
    }
    #pragma unroll
    for (int off = 16; off; off >>= 1)
        sq += __shfl_xor_sync(0xffffffffu, sq, off);

    float scale = expf(logg[o]) / sqrtf(sq);
    for (int c = lane; c < IN; c += 32) {
        int jb = c >> ibshift;
        float wv = W[o * IN + c];
        float v  = (jb == i) ? expf(wv) : (jb < i ? wv : 0.0f);
        float w  = v * scale;
        if (layer == 1) {
            g_wT1[c * 512 + o] = w;
            if (c == i) g_logw1d[o] = logf(w);
        } else if (layer == 2) {
            g_wT2[c * 512 + o] = w;
        } else if (layer == 3) {
            g_wT3[c * 512 + o] = w;
        } else {
            g_w4n[o * 512 + c] = w;
        }
    }
}

// ---------------------------------------------------------------------------
// layer 1: per block 8 batch rows; weight column cached in registers.
// ---------------------------------------------------------------------------
__global__ void gemm1_kernel(const float* __restrict__ x,
                             const float* __restrict__ bias) {
    __shared__ float xs[8][8];
    int og = threadIdx.x;
    int b0 = blockIdx.x * 8;

    float w[8];
    #pragma unroll
    for (int k = 0; k < 8; k++) w[k] = g_wT1[k * 512 + og];
    float lw = g_logw1d[og];
    float bz = bias[og];

    if (og < 64) xs[og >> 3][og & 7] = x[b0 * 8 + og];
    __syncthreads();

    #pragma unroll
    for (int r = 0; r < 8; r++) {
        float acc = bz;
        #pragma unroll
        for (int k = 0; k < 8; k++) acc += w[k] * xs[r][k];
        float ay = fabsf(acc);
        float E  = __expf(-2.0f * ay);
        float rc = __fdividef(1.0f, 1.0f + E);
        int b = b0 + r;
        g_h1[b * 512 + og]   = copysignf((1.0f - E) * rc, acc);
        g_sldA[b * 512 + og] = lw + TWO_LN2 - 2.0f * ay + __logf(rc * rc);
    }
}

// ---------------------------------------------------------------------------
// fused middle layer (2,3): persistent worklist + double-buffered masked GEMM
// + tanh + sld logsumexp update. BM=BN=64, BK=32, 256 threads, 4x4/thread.
// Item t (0..255): i = 7 - (t>>5) [heaviest first], m-block = t & 31.
// Serpentine over grid=NSM -> each CTA's total work ~9.3 k-tiles
// (deterministic per-CTA balance; never rely on SM pairing).
// Smem union: As/Bs double buffers alias epilogue's Ps/wdS.
// ---------------------------------------------------------------------------
__global__ __launch_bounds__(256) void layer_mid_kernel(int layer,
                                                        const float* __restrict__ bias) {
    const float* A    = (layer == 2) ? g_h1  : g_h2;
    const float* wT   = (layer == 2) ? g_wT2 : g_wT3;
    float*       Hout = (layer == 2) ? g_h2  : g_h3;
    const float* Sin  = (layer == 2) ? g_sldA : g_sldB;
    float*       Sout = (layer == 2) ? g_sldB : g_sldA;

    __shared__ __align__(16) float blob[2 * 2 * 32 * 68];   // 34816 B
    __shared__ float mrow[64];

    float (*As)[32][68] = (float (*)[32][68])(blob);
    float (*Bs)[32][68] = (float (*)[32][68])(blob + 2 * 32 * 68);
    float (*Ps)[68]     = (float (*)[68])(blob);               // 64x68
    float (*wdS)[68]    = (float (*)[68])(blob + 2 * 32 * 68); // 64x68

    int tid = threadIdx.x;
    int tx = tid & 15, ty = tid >> 4;
    int am = tid >> 2, ak = (tid & 3) * 4;   // A-load map
    int bk = tid >> 4, bn = (tid & 15) * 4;  // B-load map
    int G = gridDim.x;

    for (int r = 0;; r++) {
        int t = r * G + ((r & 1) ? (G - 1 - (int)blockIdx.x) : (int)blockIdx.x);
        if (t >= 256) break;

        int i  = 7 - (t >> 5);
        int n0 = i * 64;
        int m0 = (t & 31) * 64;
        int ntiles = (i + 1) * 2;            // BK=32 tiles (mask skip)

        const float* Aptr = A  + (m0 + am) * 512 + ak;
        const float* Bptr = wT + bk * 512 + n0 + bn;

        float4 a0, a1, b0, b1;
        a0 = *(const float4*)(Aptr);
        a1 = *(const float4*)(Aptr + 16);
        b0 = *(const float4*)(Bptr);
        b1 = *(const float4*)(Bptr + 16 * 512);
        {   // stash into buffer 0
            As[0][ak + 0][am] = a0.x; As[0][ak + 1][am] = a0.y;
            As[0][ak + 2][am] = a0.z; As[0][ak + 3][am] = a0.w;
            As[0][16 + ak + 0][am] = a1.x; As[0][16 + ak + 1][am] = a1.y;
            As[0][16 + ak + 2][am] = a1.z; As[0][16 + ak + 3][am] = a1.w;
            *(float4*)(&Bs[0][bk][bn])      = b0;
            *(float4*)(&Bs[0][bk + 16][bn]) = b1;
        }
        __syncthreads();

        float acc[4][4] = {};

        for (int kt = 0; kt < ntiles; kt++) {
            int cur = kt & 1;
            bool more = (kt + 1 < ntiles);
            if (more) {
                int k0 = (kt + 1) * 32;
                a0 = *(const float4*)(Aptr + k0);
                a1 = *(const float4*)(Aptr + k0 + 16);
                b0 = *(const float4*)(Bptr + k0 * 512);
                b1 = *(const float4*)(Bptr + (k0 + 16) * 512);
            }
            #pragma unroll
            for (int k = 0; k < 32; k++) {
                float4 a  = *(const float4*)(&As[cur][k][ty * 4]);
                float4 bq = *(const float4*)(&Bs[cur][k][tx * 4]);
                acc[0][0] += a.x * bq.x; acc[0][1] += a.x * bq.y;
                acc[0][2] += a.x * bq.z; acc[0][3] += a.x * bq.w;
                acc[1][0] += a.y * bq.x; acc[1][1] += a.y * bq.y;
                acc[1][2] += a.y * bq.z; acc[1][3] += a.y * bq.w;
                acc[2][0] += a.z * bq.x; acc[2][1] += a.z * bq.y;
                acc[2][2] += a.z * bq.z; acc[2][3] += a.z * bq.w;
                acc[3][0] += a.w * bq.x; acc[3][1] += a.w * bq.y;
                acc[3][2] += a.w * bq.z; acc[3][3] += a.w * bq.w;
            }
            if (more) {
                int nxt = cur ^ 1;
                As[nxt][ak + 0][am] = a0.x; As[nxt][ak + 1][am] = a0.y;
                As[nxt][ak + 2][am] = a0.z; As[nxt][ak + 3][am] = a0.w;
                As[nxt][16 + ak + 0][am] = a1.x; As[nxt][16 + ak + 1][am] = a1.y;
                As[nxt][16 + ak + 2][am] = a1.z; As[nxt][16 + ak + 3][am] = a1.w;
                *(float4*)(&Bs[nxt][bk][bn])      = b0;
                *(float4*)(&Bs[nxt][bk + 16][bn]) = b1;
            }
            __syncthreads();
        }
        // blob now free (last sync passed) -> epilogue reuses it as Ps/wdS

        // diag weight block from L2: wdS[j][o] = wT[(i*64+j)*512 + i*64+o]
        for (int idx = tid; idx < 4096; idx += 256) {
            int o = idx & 63, j = idx >> 6;
            wdS[j][o] = wT[(n0 + j) * 512 + n0 + o];
        }

        // sld tile load + row max (row = 4 contiguous lanes -> shfl reduce)
        int row = tid >> 2, q = tid & 3;
        const float4* sp = (const float4*)(Sin + (m0 + row) * 512 + n0 + q * 16);
        float4 v4[4];
        float mx = -1e30f;
        #pragma unroll
        for (int c = 0; c < 4; c++) {
            v4[c] = sp[c];
            mx = fmaxf(mx, fmaxf(fmaxf(v4[c].x, v4[c].y), fmaxf(v4[c].z, v4[c].w)));
        }
        mx = fmaxf(mx, __shfl_xor_sync(0xffffffffu, mx, 1));
        mx = fmaxf(mx, __shfl_xor_sync(0xffffffffu, mx, 2));
        if (q == 0) mrow[row] = mx;

        {   // exponentiate into Ps[j][m]
            #pragma unroll
            for (int c = 0; c < 4; c++) {
                int j = q * 16 + c * 4;
                Ps[j + 0][row] = __expf(v4[c].x - mx);
                Ps[j + 1][row] = __expf(v4[c].y - mx);
                Ps[j + 2][row] = __expf(v4[c].z - mx);
                Ps[j + 3][row] = __expf(v4[c].w - mx);
            }
        }
        __syncthreads();

        // mini-GEMM: Q[m][o] = sum_j P[m][j] * wd[o][j]
        float qacc[4][4] = {};
        #pragma unroll 8
        for (int j = 0; j < 64; j++) {
            float4 a  = *(const float4*)(&Ps[j][ty * 4]);
            float4 bq = *(const float4*)(&wdS[j][tx * 4]);
            qacc[0][0] += a.x * bq.x; qacc[0][1] += a.x * bq.y;
            qacc[0][2] += a.x * bq.z; qacc[0][3] += a.x * bq.w;
            qacc[1][0] += a.y * bq.x; qacc[1][1] += a.y * bq.y;
            qacc[1][2] += a.y * bq.z; qacc[1][3] += a.y * bq.w;
            qacc[2][0] += a.z * bq.x; qacc[2][1] += a.z * bq.y;
            qacc[2][2] += a.z * bq.z; qacc[2][3] += a.z * bq.w;
            qacc[3][0] += a.w * bq.x; qacc[3][1] += a.w * bq.y;
            qacc[3][2] += a.w * bq.z; qacc[3][3] += a.w * bq.w;
        }

        // epilogue: h = tanh(y), sld_out in one logf; vectorized stores
        float4 bz4 = *(const float4*)(bias + n0 + tx * 4);
        float bzv[4] = {bz4.x, bz4.y, bz4.z, bz4.w};
        #pragma unroll
        for (int ii = 0; ii < 4; ii++) {
            int m = m0 + ty * 4 + ii;
            float mr = mrow[ty * 4 + ii];
            float4 h4, s4;
            float* hp  = (float*)&h4;
            float* spv = (float*)&s4;
            #pragma unroll
            for (int jj = 0; jj < 4; jj++) {
                float y  = acc[ii][jj] + bzv[jj];
                float ay = fabsf(y);
                float E  = __expf(-2.0f * ay);
                float rc = __fdividef(1.0f, 1.0f + E);
                hp[jj]  = copysignf((1.0f - E) * rc, y);
                spv[jj] = mr + TWO_LN2 - 2.0f * ay + __logf(qacc[ii][jj] * rc * rc);
            }
            *(float4*)(&Hout[m * 512 + n0 + tx * 4]) = h4;
            *(float4*)(&Sout[m * 512 + n0 + tx * 4]) = s4;
        }
        __syncthreads();   // guard smem reuse by next item
    }
}

// ---------------------------------------------------------------------------
// fused layer 4: block handles 8 batch rows; w4 cached in smem once.
// warp i handles data dim i: 512-dot + tanh -> out[0:16384]; sld finale ->
// out[16384:32768].
// ---------------------------------------------------------------------------
__global__ void layer_last_kernel(const float* __restrict__ bias,
                                  float* __restrict__ out) {
    __shared__ float wsm[8 * 512];
    int tid = threadIdx.x;
    for (int idx = tid; idx < 4096; idx += 256) wsm[idx] = g_w4n[idx];
    __syncthreads();

    int i = tid >> 5, lane = tid & 31;
    float bz = bias[i];
    float wd0 = wsm[i * 512 + i * 64 + lane];
    float wd1 = wsm[i * 512 + i * 64 + lane + 32];

    int b0 = blockIdx.x * 8;
    #pragma unroll
    for (int r = 0; r < 8; r++) {
        int b = b0 + r;
        const float* hp = g_h3 + b * 512;
        float acc = 0.0f;
        #pragma unroll 4
        for (int k = lane; k < 512; k += 32) acc += hp[k] * wsm[i * 512 + k];
        #pragma unroll
        for (int off = 16; off; off >>= 1)
            acc += __shfl_xor_sync(0xffffffffu, acc, off);

        float y  = acc + bz;
        float ay = fabsf(y);
        float E  = __expf(-2.0f * ay);
        float rc = __fdividef(1.0f, 1.0f + E);

        const float* sp = g_sldA + b * 512 + i * 64;
        float s0 = sp[lane], s1 = sp[lane + 32];
        float m = fmaxf(s0, s1);
        #pragma unroll
        for (int off = 16; off; off >>= 1)
            m = fmaxf(m, __shfl_xor_sync(0xffffffffu, m, off));
        float p0 = __expf(s0 - m), p1 = __expf(s1 - m);
        float a = p0 * wd0 + p1 * wd1;
        #pragma unroll
        for (int off = 16; off; off >>= 1)
            a += __shfl_xor_sync(0xffffffffu, a, off);

        if (lane == 0) {
            out[b * 8 + i]           = copysignf((1.0f - E) * rc, y);
            out[B_ * D_ + b * 8 + i] = m + TWO_LN2 - 2.0f * ay + __logf(a * rc * rc);
        }
    }
}

// ---------------------------------------------------------------------------
extern "C" void kernel_launch(void* const* d_in, const int* in_sizes, int n_in,
                              void* d_out, int out_size) {
    (void)in_sizes; (void)n_in; (void)out_size;
    const float* x  = (const float*)d_in[0];
    const float* W1 = (const float*)d_in[1];
    const float* g1 = (const float*)d_in[2];
    const float* b1 = (const float*)d_in[3];
    const float* W2 = (const float*)d_in[4];
    const float* g2 = (const float*)d_in[5];
    const float* b2 = (const float*)d_in[6];
    const float* W3 = (const float*)d_in[7];
    const float* g3 = (const float*)d_in[8];
    const float* b3 = (const float*)d_in[9];
    const float* W4 = (const float*)d_in[10];
    const float* g4 = (const float*)d_in[11];
    const float* b4 = (const float*)d_in[12];
    float* out = (float*)d_out;

    prep_all_kernel<<<193, dim3(32, 8)>>>(W1, g1, W2, g2, W3, g3, W4, g4);
    gemm1_kernel<<<256, 512>>>(x, b1);
    layer_mid_kernel<<<NSM, 256>>>(2, b2);
    layer_mid_kernel<<<NSM, 256>>>(3, b3);
    layer_last_kernel<<<256, 256>>>(b4, out);
}